// round 2
// baseline (speedup 1.0000x reference)
#include <cuda_runtime.h>
#include <math.h>
#include <stdint.h>

// Problem constants
#define TLEN 4096
#define BSZ 8

// ---------------- device scratch (no allocation allowed) ----------------
__device__ float g_x1[BSZ * 64 * TLEN];
__device__ float g_x2[BSZ * 128 * TLEN];
__device__ float g_x3[BSZ * 256 * TLEN];
__device__ float g_x4[BSZ * 512 * TLEN];
__device__ float g_x5[BSZ * 512 * TLEN];
__device__ float g_zqT[BSZ * 512 * TLEN];          // z_q in [b][d][t] layout
__device__ float g_w2T[64 * 5 * 128];
__device__ float g_w3T[128 * 5 * 256];
__device__ float g_w4T[256 * 3 * 512];
__device__ float g_w5T[512 * 3 * 512];
__device__ float g_hwT[512 * 256];                 // head weights [d][h*64+v]
__device__ float g_part[2048];                     // vq-loss partials (32*8*8)

// Output packing offsets (float32 concat of (a_tokens, b_logits, vq_loss))
#define OFF_A 0
#define OFF_B (BSZ * 8 * TLEN)                     // 262144
#define OFF_L (OFF_B + BSZ * 4 * TLEN * 64)        // 8650752

// ---------------- conv1: Cin=1, k=7, ELU ----------------
__global__ void conv1_kernel(const float* __restrict__ audio,
                             const float* __restrict__ w1,
                             const float* __restrict__ b1,
                             float* __restrict__ y) {
    __shared__ float sx[128 + 6];
    __shared__ float sw[64 * 7];
    __shared__ float sb[64];
    const int b = blockIdx.y;
    const int t0 = blockIdx.x * 128;
    const int tid = threadIdx.x;

    for (int i = tid; i < 134; i += 128) {
        int t = t0 - 6 + i;
        sx[i] = (t >= 0) ? audio[(size_t)b * TLEN + t] : 0.f;
    }
    for (int i = tid; i < 448; i += 128) sw[i] = w1[i];
    if (tid < 64) sb[tid] = b1[tid];
    __syncthreads();

    float xv[7];
#pragma unroll
    for (int j = 0; j < 7; j++) xv[j] = sx[tid + j];

    for (int c = 0; c < 64; c++) {
        float acc = sb[c];
#pragma unroll
        for (int j = 0; j < 7; j++) acc += sw[c * 7 + j] * xv[j];
        acc = acc > 0.f ? acc : expm1f(acc);
        y[((size_t)b * 64 + c) * TLEN + t0 + tid] = acc;
    }
}

// ---------------- weight transposes ----------------
__global__ void transpose_w(const float* __restrict__ w, float* __restrict__ wT,
                            int CIN, int COUT, int K) {
    int i = blockIdx.x * 256 + threadIdx.x;
    int total = CIN * K * COUT;
    if (i < total) {
        int co = i % COUT;
        int j = (i / COUT) % K;
        int ci = i / (COUT * K);
        wT[i] = w[((size_t)co * CIN + ci) * K + j];
    }
}

__global__ void transpose_head(const float* __restrict__ hw, float* __restrict__ hwT) {
    int i = blockIdx.x * 256 + threadIdx.x;   // total 512*256
    if (i < 512 * 256) {
        int co = i % 256;       // h*64+v
        int d = i / 256;
        int h = co >> 6, v = co & 63;
        hwT[i] = hw[((size_t)h * 512 + d) * 64 + v];
    }
}

// ---------------- generic conv-as-GEMM, 128x128 tile, 8x8 per thread -------
// x: [B][CIN][T], wT: [CIN*K][COUT], y: conv -> [B][COUT][T]; HEAD -> bhtv
template <int CIN, int COUT, int K, int CI_CHUNK, int ELU, int HEAD>
__global__ __launch_bounds__(256)
void conv_gemm(const float* __restrict__ x, const float* __restrict__ wT,
               const float* __restrict__ bias, float* __restrict__ y) {
    constexpr int TT = 128;
    constexpr int CO_TILE = 128;
    constexpr int XROW = TT + 8;                 // 136, covers halo K-1<=6
    constexpr int NXF4 = (8 + K - 1 + 3) / 4;    // float4s of x per thread

    __shared__ float xs[CI_CHUNK][XROW];
    __shared__ float ws[CI_CHUNK][K][CO_TILE];

    const int b = blockIdx.z;
    const int t0 = blockIdx.x * TT;
    const int co0 = blockIdx.y * CO_TILE;
    const int tid = threadIdx.x;
    const int tx = tid & 15;      // t groups
    const int ty = tid >> 4;      // co groups
    const int tb = tx * 8;
    const int cb = ty * 8;

    float acc[8][8];
#pragma unroll
    for (int r = 0; r < 8; r++) {
        float bb = bias[co0 + cb + r];
#pragma unroll
        for (int j = 0; j < 8; j++) acc[r][j] = bb;
    }

#pragma unroll 1
    for (int ci0 = 0; ci0 < CIN; ci0 += CI_CHUNK) {
        __syncthreads();
        // load x tile (coalesced over t)
        for (int i = tid; i < CI_CHUNK * XROW; i += 256) {
            int cc = i / XROW, p = i % XROW;
            int t = t0 - (K - 1) + p;
            float v = 0.f;
            if (t >= 0 && t < TLEN)
                v = x[((size_t)b * CIN + ci0 + cc) * TLEN + t];
            xs[cc][p] = v;
        }
        // load w tile (coalesced over co)
        for (int i = tid; i < CI_CHUNK * K * CO_TILE; i += 256) {
            int cc = i / (K * CO_TILE);
            int rem = i % (K * CO_TILE);
            int j = rem / CO_TILE;
            int co = rem % CO_TILE;
            ws[cc][j][co] = wT[((size_t)(ci0 + cc) * K + j) * COUT + co0 + co];
        }
        __syncthreads();

#pragma unroll 1
        for (int cc = 0; cc < CI_CHUNK; cc++) {
            float xv[NXF4 * 4];
#pragma unroll
            for (int q = 0; q < NXF4; q++)
                *(float4*)&xv[q * 4] = *(const float4*)&xs[cc][tb + q * 4];
#pragma unroll
            for (int j = 0; j < K; j++) {
                float wv[8];
                *(float4*)&wv[0] = *(const float4*)&ws[cc][j][cb];
                *(float4*)&wv[4] = *(const float4*)&ws[cc][j][cb + 4];
#pragma unroll
                for (int r = 0; r < 8; r++)
#pragma unroll
                    for (int lt = 0; lt < 8; lt++)
                        acc[r][lt] += wv[r] * xv[lt + j];
            }
        }
    }

    if (HEAD) {
        // co = h*64 + v; each thread's 8 co stay within one head (8 | 64)
        const int h = (co0 + cb) >> 6;
        const int v0 = (co0 + cb) & 63;
#pragma unroll
        for (int lt = 0; lt < 8; lt++) {
            int t = t0 + tb + lt;
            float4 o0 = make_float4(acc[0][lt], acc[1][lt], acc[2][lt], acc[3][lt]);
            float4 o1 = make_float4(acc[4][lt], acc[5][lt], acc[6][lt], acc[7][lt]);
            float* base = &y[(((size_t)b * 4 + h) * TLEN + t) * 64 + v0];
            *(float4*)base = o0;
            *(float4*)(base + 4) = o1;
        }
    } else {
#pragma unroll
        for (int r = 0; r < 8; r++) {
            float o[8];
#pragma unroll
            for (int lt = 0; lt < 8; lt++) {
                float a = acc[r][lt];
                if (ELU) a = a > 0.f ? a : expm1f(a);
                o[lt] = a;
            }
            float* base = &y[((size_t)b * COUT + co0 + cb + r) * TLEN + t0 + tb];
            *(float4*)base = *(float4*)&o[0];
            *(float4*)(base + 4) = *(float4*)&o[4];
        }
    }
}

// ---------------- VQ: fused dist-GEMM + argmin + gather + loss ----------------
// block: 256 thr, tile 128 tokens x 128 codes (8 chunks over 1024 codes)
// smem floats: ztT 64*128, ctT 64*132 (aliased by qs later), znorm 128,
//              cnorm 128, redv 2048, redi 2048(int), besti 128(int)
#define VQ_ZT 0
#define VQ_CT (64 * 128)
#define VQ_ZN (VQ_CT + 64 * 132)
#define VQ_CN (VQ_ZN + 128)
#define VQ_RV (VQ_CN + 128)
#define VQ_RI (VQ_RV + 2048)
#define VQ_BI (VQ_RI + 2048)
#define VQ_SMEM_FLOATS (VQ_BI + 128)
#define VQ_SMEM_BYTES (VQ_SMEM_FLOATS * 4)

__global__ __launch_bounds__(256)
void vq_kernel(const float* __restrict__ x5, const float* __restrict__ cbk,
               float* __restrict__ zqT, float* __restrict__ out_a,
               float* __restrict__ partial) {
    extern __shared__ float sm[];
    float* ztT = sm + VQ_ZT;          // [64][128]
    float* ctT = sm + VQ_CT;          // [64][132]
    float* znorm = sm + VQ_ZN;        // [128]
    float* cnorm = sm + VQ_CN;        // [128]
    float* redv = sm + VQ_RV;         // [128][16]
    int*   redi = (int*)(sm + VQ_RI); // [128][16]
    int*   besti = (int*)(sm + VQ_BI);// [128]
    float* qs = ctT;                  // alias: reused after chunk loop

    const int b = blockIdx.z, g = blockIdx.y;
    const int t0 = blockIdx.x * 128;
    const int tid = threadIdx.x;
    const int tx = tid & 15;          // token groups
    const int ty = tid >> 4;          // code groups
    const int trow = tx * 8;          // 8 tokens per thread
    const int cbase = ty * 8;         // 8 codes per thread (within chunk)

    // load z tile (coalesced over t), layout [d][t]
    for (int i = tid; i < 64 * 128; i += 256) {
        int d = i >> 7, lt = i & 127;
        ztT[d * 128 + lt] = x5[(((size_t)b * 512) + (g << 6) + d) * TLEN + t0 + lt];
    }
    __syncthreads();
    if (tid < 128) {
        float s = 0.f;
#pragma unroll 8
        for (int d = 0; d < 64; d++) { float v = ztT[d * 128 + tid]; s += v * v; }
        znorm[tid] = s;
    }
    __syncthreads();

    float zn[8];
#pragma unroll
    for (int a = 0; a < 8; a++) zn[a] = znorm[trow + a];

    float bv[8];
    int bi[8];
#pragma unroll
    for (int a = 0; a < 8; a++) { bv[a] = 3.4e38f; bi[a] = 0; }

#pragma unroll 1
    for (int k0 = 0; k0 < 1024; k0 += 128) {
        __syncthreads();   // previous chunk's compute done before ctT reuse
        // load code chunk transposed: ctT[d][kk]
        for (int i = tid; i < 64 * 128; i += 256) {
            int kk = i >> 6;            // 0..127
            int d = i & 63;
            ctT[d * 132 + kk] = cbk[((size_t)g * 1024 + k0 + kk) * 64 + d];
        }
        __syncthreads();
        if (tid < 128) {
            float s = 0.f;
#pragma unroll 8
            for (int d = 0; d < 64; d++) { float v = ctT[d * 132 + tid]; s += v * v; }
            cnorm[tid] = s;
        }
        __syncthreads();

        float acc[8][8];
#pragma unroll
        for (int a = 0; a < 8; a++)
#pragma unroll
            for (int c = 0; c < 8; c++) acc[a][c] = 0.f;

#pragma unroll 4
        for (int d = 0; d < 64; d++) {
            float zz[8], cc[8];
            *(float4*)&zz[0] = *(const float4*)&ztT[d * 128 + trow];
            *(float4*)&zz[4] = *(const float4*)&ztT[d * 128 + trow + 4];
            *(float4*)&cc[0] = *(const float4*)&ctT[d * 132 + cbase];
            *(float4*)&cc[4] = *(const float4*)&ctT[d * 132 + cbase + 4];
#pragma unroll
            for (int a = 0; a < 8; a++)
#pragma unroll
                for (int c = 0; c < 8; c++) acc[a][c] += zz[a] * cc[c];
        }

        float cn[8];
#pragma unroll
        for (int c = 0; c < 8; c++) cn[c] = cnorm[cbase + c];
#pragma unroll
        for (int a = 0; a < 8; a++) {
#pragma unroll
            for (int c = 0; c < 8; c++) {
                float dist = zn[a] + cn[c] - 2.f * acc[a][c];
                int idx = k0 + cbase + c;
                if (dist < bv[a]) { bv[a] = dist; bi[a] = idx; }  // strict < keeps first
            }
        }
    }

    // cross-thread argmin reduction (16 contributors per token)
    __syncthreads();
#pragma unroll
    for (int a = 0; a < 8; a++) {
        int tok = trow + a;
        redv[tok * 16 + ty] = bv[a];
        redi[tok * 16 + ty] = bi[a];
    }
    __syncthreads();
    if (tid < 128) {
        float best = redv[tid * 16];
        int bidx = redi[tid * 16];
#pragma unroll
        for (int s = 1; s < 16; s++) {
            float v = redv[tid * 16 + s];
            int ii = redi[tid * 16 + s];
            if (v < best || (v == best && ii < bidx)) { best = v; bidx = ii; }
        }
        besti[tid] = bidx;
        out_a[((size_t)b * 8 + g) * TLEN + t0 + tid] = (float)bidx;
    }
    __syncthreads();

    // gather q (coalesced codebook reads), exact loss, stage q for coalesced store
    float ls = 0.f;
    for (int i = tid; i < 64 * 128; i += 256) {
        int d = i & 63, lt = i >> 6;
        float qv = cbk[((size_t)g * 1024 + besti[lt]) * 64 + d];
        float df = qv - ztT[d * 128 + lt];
        ls += df * df;
        qs[d * 132 + lt] = qv;
    }
    __syncthreads();
    for (int i = tid; i < 64 * 128; i += 256) {
        int lt = i & 127, d = i >> 7;
        zqT[(((size_t)b * 512) + (g << 6) + d) * TLEN + t0 + lt] = qs[d * 132 + lt];
    }

    // deterministic block loss reduction (redv reused)
    redv[tid] = ls;
    __syncthreads();
    for (int s = 128; s > 0; s >>= 1) {
        if (tid < s) redv[tid] += redv[tid + s];
        __syncthreads();
    }
    if (tid == 0)
        partial[((size_t)b * 8 + g) * 32 + blockIdx.x] = redv[0];
}

// ---------------- final deterministic loss sum ----------------
__global__ void loss_kernel(const float* __restrict__ partial, float* __restrict__ out) {
    __shared__ float s[256];
    int tid = threadIdx.x;
    float v = 0.f;
    for (int i = tid; i < 2048; i += 256) v += partial[i];
    s[tid] = v;
    __syncthreads();
    for (int k = 128; k > 0; k >>= 1) {
        if (tid < k) s[tid] += s[tid + k];
        __syncthreads();
    }
    if (tid == 0) out[OFF_L] = s[0] * (1.f / (8.f * 4096.f * 64.f));
}

// ---------------- launch ----------------
extern "C" void kernel_launch(void* const* d_in, const int* in_sizes, int n_in,
                              void* d_out, int out_size) {
    const float* audio = (const float*)d_in[0];
    const float* w1 = (const float*)d_in[1];
    const float* b1 = (const float*)d_in[2];
    const float* w2 = (const float*)d_in[3];
    const float* b2 = (const float*)d_in[4];
    const float* w3 = (const float*)d_in[5];
    const float* b3 = (const float*)d_in[6];
    const float* w4 = (const float*)d_in[7];
    const float* b4 = (const float*)d_in[8];
    const float* w5 = (const float*)d_in[9];
    const float* b5 = (const float*)d_in[10];
    const float* codebooks = (const float*)d_in[11];
    const float* head_w = (const float*)d_in[12];
    const float* head_b = (const float*)d_in[13];
    float* out = (float*)d_out;

    float *x1, *x2, *x3, *x4, *x5, *zqT, *w2T, *w3T, *w4T, *w5T, *hwT, *part;
    cudaGetSymbolAddress((void**)&x1, g_x1);
    cudaGetSymbolAddress((void**)&x2, g_x2);
    cudaGetSymbolAddress((void**)&x3, g_x3);
    cudaGetSymbolAddress((void**)&x4, g_x4);
    cudaGetSymbolAddress((void**)&x5, g_x5);
    cudaGetSymbolAddress((void**)&zqT, g_zqT);
    cudaGetSymbolAddress((void**)&w2T, g_w2T);
    cudaGetSymbolAddress((void**)&w3T, g_w3T);
    cudaGetSymbolAddress((void**)&w4T, g_w4T);
    cudaGetSymbolAddress((void**)&w5T, g_w5T);
    cudaGetSymbolAddress((void**)&hwT, g_hwT);
    cudaGetSymbolAddress((void**)&part, g_part);

    cudaFuncSetAttribute(vq_kernel, cudaFuncAttributeMaxDynamicSharedMemorySize,
                         VQ_SMEM_BYTES);

    // weight prep
    transpose_w<<<(64 * 5 * 128 + 255) / 256, 256>>>(w2, w2T, 64, 128, 5);
    transpose_w<<<(128 * 5 * 256 + 255) / 256, 256>>>(w3, w3T, 128, 256, 5);
    transpose_w<<<(256 * 3 * 512 + 255) / 256, 256>>>(w4, w4T, 256, 512, 3);
    transpose_w<<<(512 * 3 * 512 + 255) / 256, 256>>>(w5, w5T, 512, 512, 3);
    transpose_head<<<(512 * 256 + 255) / 256, 256>>>(head_w, hwT);

    // encoder
    conv1_kernel<<<dim3(32, 8), 128>>>(audio, w1, b1, x1);
    conv_gemm<64, 128, 5, 8, 1, 0><<<dim3(32, 1, 8), 256>>>(x1, w2T, b2, x2);
    conv_gemm<128, 256, 5, 8, 1, 0><<<dim3(32, 2, 8), 256>>>(x2, w3T, b3, x3);
    conv_gemm<256, 512, 3, 16, 1, 0><<<dim3(32, 4, 8), 256>>>(x3, w4T, b4, x4);
    conv_gemm<512, 512, 3, 16, 0, 0><<<dim3(32, 4, 8), 256>>>(x4, w5T, b5, x5);

    // VQ + heads + loss
    vq_kernel<<<dim3(32, 8, 8), 256, VQ_SMEM_BYTES>>>(x5, codebooks, zqT, out + OFF_A, part);
    conv_gemm<512, 256, 1, 16, 0, 1><<<dim3(32, 2, 8), 256>>>(zqT, hwT, head_b, out + OFF_B);
    loss_kernel<<<1, 256>>>(part, out);
}

// round 3
// speedup vs baseline: 1.1550x; 1.1550x over previous
#include <cuda_runtime.h>
#include <math.h>
#include <stdint.h>

// Problem constants
#define TLEN 4096
#define BSZ 8

typedef unsigned long long ull;

// Packed fp32x2 helpers (Blackwell sm_100a+): full-rate fp32 FMA
#define FMA2(acc, a, b) \
    asm("fma.rn.f32x2 %0, %1, %2, %3;" : "=l"(acc) : "l"(a), "l"(b), "l"(acc))
#define PACKB(d, s) \
    asm("mov.b64 %0, {%1, %1};" : "=l"(d) : "f"(s))
#define PACK2(d, lo, hi) \
    asm("mov.b64 %0, {%1, %2};" : "=l"(d) : "f"(lo), "f"(hi))
#define UNPACK2(lo, hi, s) \
    asm("mov.b64 {%0, %1}, %2;" : "=f"(lo), "=f"(hi) : "l"(s))

// 16B-chunk XOR swizzle: kills 2-way smem phase conflicts for 32B-strided lanes
__device__ __forceinline__ int swz(int c) { return c ^ ((c >> 3) & 3); }
// swizzled float offset within a row, given logical float offset p
__device__ __forceinline__ int swzf(int p) { return (swz(p >> 2) << 2) | (p & 3); }

// ---------------- device scratch (no allocation allowed) ----------------
__device__ float g_x1[BSZ * 64 * TLEN];
__device__ float g_x2[BSZ * 128 * TLEN];
__device__ float g_x3[BSZ * 256 * TLEN];
__device__ float g_x4[BSZ * 512 * TLEN];
__device__ float g_x5[BSZ * 512 * TLEN];
__device__ float g_zqT[BSZ * 512 * TLEN];          // z_q in [b][d][t] layout
__device__ float g_w2T[64 * 5 * 128];
__device__ float g_w3T[128 * 5 * 256];
__device__ float g_w4T[256 * 3 * 512];
__device__ float g_w5T[512 * 3 * 512];
__device__ float g_hwT[512 * 256];                 // head weights [d][h*64+v]
__device__ float g_part[2048];                     // vq-loss partials (32*8*8)

// Output packing offsets (float32 concat of (a_tokens, b_logits, vq_loss))
#define OFF_A 0
#define OFF_B (BSZ * 8 * TLEN)                     // 262144
#define OFF_L (OFF_B + BSZ * 4 * TLEN * 64)        // 8650752

// ---------------- fused weight prep (single launch) ----------------
__device__ __forceinline__ void tr_seg(int local, const float* __restrict__ w,
                                       float* __restrict__ wT,
                                       int CIN, int COUT, int K) {
    int co = local % COUT;
    int j = (local / COUT) % K;
    int ci = local / (COUT * K);
    wT[local] = w[((size_t)co * CIN + ci) * K + j];
}

#define N_W2 (64 * 5 * 128)
#define N_W3 (128 * 5 * 256)
#define N_W4 (256 * 3 * 512)
#define N_W5 (512 * 3 * 512)
#define N_HW (512 * 256)
#define N_PREP (N_W2 + N_W3 + N_W4 + N_W5 + N_HW)

__global__ void prep_kernel(const float* __restrict__ w2, const float* __restrict__ w3,
                            const float* __restrict__ w4, const float* __restrict__ w5,
                            const float* __restrict__ hw,
                            float* __restrict__ w2T, float* __restrict__ w3T,
                            float* __restrict__ w4T, float* __restrict__ w5T,
                            float* __restrict__ hwT) {
    int i = blockIdx.x * 256 + threadIdx.x;
    if (i < N_W2) { tr_seg(i, w2, w2T, 64, 128, 5); return; }
    i -= N_W2;
    if (i < N_W3) { tr_seg(i, w3, w3T, 128, 256, 5); return; }
    i -= N_W3;
    if (i < N_W4) { tr_seg(i, w4, w4T, 256, 512, 3); return; }
    i -= N_W4;
    if (i < N_W5) { tr_seg(i, w5, w5T, 512, 512, 3); return; }
    i -= N_W5;
    if (i < N_HW) {
        int co = i % 256;       // h*64+v
        int d = i / 256;
        int h = co >> 6, v = co & 63;
        hwT[i] = hw[((size_t)h * 512 + d) * 64 + v];
    }
}

// ---------------- conv1: Cin=1, k=7, ELU ----------------
__global__ void conv1_kernel(const float* __restrict__ audio,
                             const float* __restrict__ w1,
                             const float* __restrict__ b1,
                             float* __restrict__ y) {
    __shared__ float sx[128 + 6];
    __shared__ float sw[64 * 7];
    __shared__ float sb[64];
    const int b = blockIdx.y;
    const int t0 = blockIdx.x * 128;
    const int tid = threadIdx.x;

    for (int i = tid; i < 134; i += 128) {
        int t = t0 - 6 + i;
        sx[i] = (t >= 0) ? audio[(size_t)b * TLEN + t] : 0.f;
    }
    for (int i = tid; i < 448; i += 128) sw[i] = w1[i];
    if (tid < 64) sb[tid] = b1[tid];
    __syncthreads();

    float xv[7];
#pragma unroll
    for (int j = 0; j < 7; j++) xv[j] = sx[tid + j];

    for (int c = 0; c < 64; c++) {
        float acc = sb[c];
#pragma unroll
        for (int j = 0; j < 7; j++) acc += sw[c * 7 + j] * xv[j];
        acc = acc > 0.f ? acc : expm1f(acc);
        y[((size_t)b * 64 + c) * TLEN + t0 + tid] = acc;
    }
}

// ---------------- generic conv-as-GEMM, 128x128 tile, 8x8, f32x2 ----------
// x: [B][CIN][T], wT: [CIN*K][COUT], y: conv -> [B][COUT][T]; HEAD -> bhtv
template <int CIN, int COUT, int K, int CI_CHUNK, int ELU, int HEAD>
__global__ __launch_bounds__(256, 2)
void conv_gemm(const float* __restrict__ x, const float* __restrict__ wT,
               const float* __restrict__ bias, float* __restrict__ y) {
    constexpr int TT = 128;
    constexpr int CO_TILE = 128;
    constexpr int XROW = 136;                    // covers halo K-1<=6, swizzle-safe
    constexpr int NX = 8 + K - 1;                // window floats per thread
    constexpr int NXF4 = (NX + 3) / 4;           // float4 chunks

    __shared__ float xs[CI_CHUNK][XROW];
    __shared__ float ws[CI_CHUNK][K][CO_TILE];

    const int b = blockIdx.z;
    const int t0 = blockIdx.x * TT;
    const int co0 = blockIdx.y * CO_TILE;
    const int tid = threadIdx.x;
    const int tx = tid & 15;      // t groups
    const int ty = tid >> 4;      // co groups
    const int tb = tx * 8;
    const int cb = ty * 8;

    ull acc2[4][8];               // pairs over co: (cb+2rp, cb+2rp+1) x 8 t
#pragma unroll
    for (int rp = 0; rp < 4; rp++) {
        ull bb2;
        PACK2(bb2, bias[co0 + cb + 2 * rp], bias[co0 + cb + 2 * rp + 1]);
#pragma unroll
        for (int lt = 0; lt < 8; lt++) acc2[rp][lt] = bb2;
    }

#pragma unroll 1
    for (int ci0 = 0; ci0 < CIN; ci0 += CI_CHUNK) {
        __syncthreads();
        // load x tile (coalesced over t), swizzled by 16B chunk within row
        for (int i = tid; i < CI_CHUNK * XROW; i += 256) {
            int cc = i / XROW, p = i % XROW;
            int t = t0 - (K - 1) + p;
            float v = 0.f;
            if (t >= 0 && t < TLEN)
                v = x[((size_t)b * CIN + ci0 + cc) * TLEN + t];
            xs[cc][swzf(p)] = v;
        }
        // load w tile (coalesced over co)
        for (int i = tid; i < CI_CHUNK * K * CO_TILE; i += 256) {
            int cc = i / (K * CO_TILE);
            int rem = i % (K * CO_TILE);
            int j = rem / CO_TILE;
            int co = rem % CO_TILE;
            ws[cc][j][co] = wT[((size_t)(ci0 + cc) * K + j) * COUT + co0 + co];
        }
        __syncthreads();

#pragma unroll 1
        for (int cc = 0; cc < CI_CHUNK; cc++) {
            float xv[NXF4 * 4];
#pragma unroll
            for (int q = 0; q < NXF4; q++)
                *(float4*)&xv[q * 4] =
                    *(const float4*)&xs[cc][swz(tx * 2 + q) << 2];
            ull xb[NX];
#pragma unroll
            for (int p = 0; p < NX; p++) PACKB(xb[p], xv[p]);
#pragma unroll
            for (int j = 0; j < K; j++) {
                ulonglong2 w01 = *(const ulonglong2*)&ws[cc][j][cb];
                ulonglong2 w23 = *(const ulonglong2*)&ws[cc][j][cb + 4];
                ull wp[4] = {w01.x, w01.y, w23.x, w23.y};
#pragma unroll
                for (int rp = 0; rp < 4; rp++)
#pragma unroll
                    for (int lt = 0; lt < 8; lt++)
                        FMA2(acc2[rp][lt], wp[rp], xb[lt + j]);
            }
        }
    }

    // unpack accumulators
    float accs[8][8];
#pragma unroll
    for (int rp = 0; rp < 4; rp++)
#pragma unroll
        for (int lt = 0; lt < 8; lt++)
            UNPACK2(accs[2 * rp][lt], accs[2 * rp + 1][lt], acc2[rp][lt]);

    if (HEAD) {
        // co = h*64 + v; each thread's 8 co stay within one head (8 | 64)
        const int h = (co0 + cb) >> 6;
        const int v0 = (co0 + cb) & 63;
#pragma unroll
        for (int lt = 0; lt < 8; lt++) {
            int t = t0 + tb + lt;
            float4 o0 = make_float4(accs[0][lt], accs[1][lt], accs[2][lt], accs[3][lt]);
            float4 o1 = make_float4(accs[4][lt], accs[5][lt], accs[6][lt], accs[7][lt]);
            float* base = &y[(((size_t)b * 4 + h) * TLEN + t) * 64 + v0];
            *(float4*)base = o0;
            *(float4*)(base + 4) = o1;
        }
    } else {
#pragma unroll
        for (int r = 0; r < 8; r++) {
            float o[8];
#pragma unroll
            for (int lt = 0; lt < 8; lt++) {
                float a = accs[r][lt];
                if (ELU) a = a > 0.f ? a : expm1f(a);
                o[lt] = a;
            }
            float* base = &y[((size_t)b * COUT + co0 + cb + r) * TLEN + t0 + tb];
            *(float4*)base = *(float4*)&o[0];
            *(float4*)(base + 4) = *(float4*)&o[4];
        }
    }
}

// ---------------- VQ: fused dist-GEMM + argmin + gather + loss ----------------
// block: 256 thr, tile 128 tokens x 128 codes (8 chunks over 1024 codes)
#define VQ_ZT 0
#define VQ_CT (64 * 128)
#define VQ_ZN (VQ_CT + 64 * 132)
#define VQ_CN (VQ_ZN + 128)
#define VQ_RV (VQ_CN + 128)
#define VQ_RI (VQ_RV + 2048)
#define VQ_BI (VQ_RI + 2048)
#define VQ_SMEM_FLOATS (VQ_BI + 128)
#define VQ_SMEM_BYTES (VQ_SMEM_FLOATS * 4)

__global__ __launch_bounds__(256, 2)
void vq_kernel(const float* __restrict__ x5, const float* __restrict__ cbk,
               float* __restrict__ zqT, float* __restrict__ out_a,
               float* __restrict__ partial) {
    extern __shared__ float sm[];
    float* ztT = sm + VQ_ZT;          // [64][128] swizzled rows
    float* ctT = sm + VQ_CT;          // [64][132]
    float* znorm = sm + VQ_ZN;        // [128]
    float* cnorm = sm + VQ_CN;        // [128]
    float* redv = sm + VQ_RV;         // [128][16]
    int*   redi = (int*)(sm + VQ_RI); // [128][16]
    int*   besti = (int*)(sm + VQ_BI);// [128]
    float* qs = ctT;                  // alias: reused after chunk loop

    const int b = blockIdx.z, g = blockIdx.y;
    const int t0 = blockIdx.x * 128;
    const int tid = threadIdx.x;
    const int tx = tid & 15;          // token groups
    const int ty = tid >> 4;          // code groups
    const int trow = tx * 8;          // 8 tokens per thread
    const int cbase = ty * 8;         // 8 codes per thread (within chunk)

    // load z tile (coalesced over t), layout [d][t], swizzled within row
    for (int i = tid; i < 64 * 128; i += 256) {
        int d = i >> 7, lt = i & 127;
        ztT[d * 128 + swzf(lt)] =
            x5[(((size_t)b * 512) + (g << 6) + d) * TLEN + t0 + lt];
    }
    __syncthreads();
    if (tid < 128) {
        float s = 0.f;
        int off = swzf(tid);
#pragma unroll 8
        for (int d = 0; d < 64; d++) { float v = ztT[d * 128 + off]; s += v * v; }
        znorm[tid] = s;
    }
    __syncthreads();

    float zn[8];
#pragma unroll
    for (int a = 0; a < 8; a++) zn[a] = znorm[trow + a];

    float bv[8];
    int bi[8];
#pragma unroll
    for (int a = 0; a < 8; a++) { bv[a] = 3.4e38f; bi[a] = 0; }

#pragma unroll 1
    for (int k0 = 0; k0 < 1024; k0 += 128) {
        __syncthreads();   // previous chunk's compute done before ctT reuse
        // load code chunk transposed: ctT[d][kk]
        for (int i = tid; i < 64 * 128; i += 256) {
            int kk = i >> 6;            // 0..127
            int d = i & 63;
            ctT[d * 132 + kk] = cbk[((size_t)g * 1024 + k0 + kk) * 64 + d];
        }
        __syncthreads();
        if (tid < 128) {
            float s = 0.f;
#pragma unroll 8
            for (int d = 0; d < 64; d++) { float v = ctT[d * 132 + tid]; s += v * v; }
            cnorm[tid] = s;
        }
        __syncthreads();

        ull acc2[8][4];    // pairs over code: (cbase+2q, cbase+2q+1)
#pragma unroll
        for (int a = 0; a < 8; a++)
#pragma unroll
            for (int q = 0; q < 4; q++) acc2[a][q] = 0ull;

#pragma unroll 4
        for (int d = 0; d < 64; d++) {
            float zz[8];
            *(float4*)&zz[0] = *(const float4*)&ztT[d * 128 + (swz(tx * 2) << 2)];
            *(float4*)&zz[4] = *(const float4*)&ztT[d * 128 + (swz(tx * 2 + 1) << 2)];
            ull zb[8];
#pragma unroll
            for (int a = 0; a < 8; a++) PACKB(zb[a], zz[a]);
            ulonglong2 c01 = *(const ulonglong2*)&ctT[d * 132 + cbase];
            ulonglong2 c23 = *(const ulonglong2*)&ctT[d * 132 + cbase + 4];
            ull cp[4] = {c01.x, c01.y, c23.x, c23.y};
#pragma unroll
            for (int a = 0; a < 8; a++)
#pragma unroll
                for (int q = 0; q < 4; q++)
                    FMA2(acc2[a][q], zb[a], cp[q]);
        }

        float accs[8][8];
#pragma unroll
        for (int a = 0; a < 8; a++)
#pragma unroll
            for (int q = 0; q < 4; q++)
                UNPACK2(accs[a][2 * q], accs[a][2 * q + 1], acc2[a][q]);

        float cn[8];
#pragma unroll
        for (int c = 0; c < 8; c++) cn[c] = cnorm[cbase + c];
#pragma unroll
        for (int a = 0; a < 8; a++) {
#pragma unroll
            for (int c = 0; c < 8; c++) {
                float dist = zn[a] + cn[c] - 2.f * accs[a][c];
                int idx = k0 + cbase + c;
                if (dist < bv[a]) { bv[a] = dist; bi[a] = idx; }  // strict < keeps first
            }
        }
    }

    // cross-thread argmin reduction (16 contributors per token)
    __syncthreads();
#pragma unroll
    for (int a = 0; a < 8; a++) {
        int tok = trow + a;
        redv[tok * 16 + ty] = bv[a];
        redi[tok * 16 + ty] = bi[a];
    }
    __syncthreads();
    if (tid < 128) {
        float best = redv[tid * 16];
        int bidx = redi[tid * 16];
#pragma unroll
        for (int s = 1; s < 16; s++) {
            float v = redv[tid * 16 + s];
            int ii = redi[tid * 16 + s];
            if (v < best || (v == best && ii < bidx)) { best = v; bidx = ii; }
        }
        besti[tid] = bidx;
        out_a[((size_t)b * 8 + g) * TLEN + t0 + tid] = (float)bidx;
    }
    __syncthreads();

    // gather q (coalesced codebook reads), exact loss, stage q for coalesced store
    float ls = 0.f;
    for (int i = tid; i < 64 * 128; i += 256) {
        int d = i & 63, lt = i >> 6;
        float qv = cbk[((size_t)g * 1024 + besti[lt]) * 64 + d];
        float df = qv - ztT[d * 128 + swzf(lt)];
        ls += df * df;
        qs[d * 132 + lt] = qv;
    }
    __syncthreads();
    for (int i = tid; i < 64 * 128; i += 256) {
        int lt = i & 127, d = i >> 7;
        zqT[(((size_t)b * 512) + (g << 6) + d) * TLEN + t0 + lt] = qs[d * 132 + lt];
    }

    // deterministic block loss reduction (redv reused)
    redv[tid] = ls;
    __syncthreads();
    for (int s = 128; s > 0; s >>= 1) {
        if (tid < s) redv[tid] += redv[tid + s];
        __syncthreads();
    }
    if (tid == 0)
        partial[((size_t)b * 8 + g) * 32 + blockIdx.x] = redv[0];
}

// ---------------- final deterministic loss sum ----------------
__global__ void loss_kernel(const float* __restrict__ partial, float* __restrict__ out) {
    __shared__ float s[256];
    int tid = threadIdx.x;
    float v = 0.f;
    for (int i = tid; i < 2048; i += 256) v += partial[i];
    s[tid] = v;
    __syncthreads();
    for (int k = 128; k > 0; k >>= 1) {
        if (tid < k) s[tid] += s[tid + k];
        __syncthreads();
    }
    if (tid == 0) out[OFF_L] = s[0] * (1.f / (8.f * 4096.f * 64.f));
}

// ---------------- launch ----------------
extern "C" void kernel_launch(void* const* d_in, const int* in_sizes, int n_in,
                              void* d_out, int out_size) {
    const float* audio = (const float*)d_in[0];
    const float* w1 = (const float*)d_in[1];
    const float* b1 = (const float*)d_in[2];
    const float* w2 = (const float*)d_in[3];
    const float* b2 = (const float*)d_in[4];
    const float* w3 = (const float*)d_in[5];
    const float* b3 = (const float*)d_in[6];
    const float* w4 = (const float*)d_in[7];
    const float* b4 = (const float*)d_in[8];
    const float* w5 = (const float*)d_in[9];
    const float* b5 = (const float*)d_in[10];
    const float* codebooks = (const float*)d_in[11];
    const float* head_w = (const float*)d_in[12];
    const float* head_b = (const float*)d_in[13];
    float* out = (float*)d_out;

    float *x1, *x2, *x3, *x4, *x5, *zqT, *w2T, *w3T, *w4T, *w5T, *hwT, *part;
    cudaGetSymbolAddress((void**)&x1, g_x1);
    cudaGetSymbolAddress((void**)&x2, g_x2);
    cudaGetSymbolAddress((void**)&x3, g_x3);
    cudaGetSymbolAddress((void**)&x4, g_x4);
    cudaGetSymbolAddress((void**)&x5, g_x5);
    cudaGetSymbolAddress((void**)&zqT, g_zqT);
    cudaGetSymbolAddress((void**)&w2T, g_w2T);
    cudaGetSymbolAddress((void**)&w3T, g_w3T);
    cudaGetSymbolAddress((void**)&w4T, g_w4T);
    cudaGetSymbolAddress((void**)&w5T, g_w5T);
    cudaGetSymbolAddress((void**)&hwT, g_hwT);
    cudaGetSymbolAddress((void**)&part, g_part);

    cudaFuncSetAttribute(vq_kernel, cudaFuncAttributeMaxDynamicSharedMemorySize,
                         VQ_SMEM_BYTES);

    // fused weight prep (1 launch)
    prep_kernel<<<(N_PREP + 255) / 256, 256>>>(w2, w3, w4, w5, head_w,
                                               w2T, w3T, w4T, w5T, hwT);

    // encoder
    conv1_kernel<<<dim3(32, 8), 128>>>(audio, w1, b1, x1);
    conv_gemm<64, 128, 5, 8, 1, 0><<<dim3(32, 1, 8), 256>>>(x1, w2T, b2, x2);
    conv_gemm<128, 256, 5, 8, 1, 0><<<dim3(32, 2, 8), 256>>>(x2, w3T, b3, x3);
    conv_gemm<256, 512, 3, 16, 1, 0><<<dim3(32, 4, 8), 256>>>(x3, w4T, b4, x4);
    conv_gemm<512, 512, 3, 16, 0, 0><<<dim3(32, 4, 8), 256>>>(x4, w5T, b5, x5);

    // VQ + heads + loss
    vq_kernel<<<dim3(32, 8, 8), 256, VQ_SMEM_BYTES>>>(x5, codebooks, zqT, out + OFF_A, part);
    conv_gemm<512, 256, 1, 16, 0, 1><<<dim3(32, 2, 8), 256>>>(zqT, hwT, head_b, out + OFF_B);
    loss_kernel<<<1, 256>>>(part, out);
}

// round 4
// speedup vs baseline: 1.3128x; 1.1367x over previous
#include <cuda_runtime.h>
#include <math.h>
#include <stdint.h>

// Problem constants
#define TLEN 4096
#define BSZ 8

typedef unsigned long long ull;

// Packed fp32x2 helpers (Blackwell sm_100a+): full-rate fp32 FMA
#define FMA2(acc, a, b) \
    asm("fma.rn.f32x2 %0, %1, %2, %3;" : "=l"(acc) : "l"(a), "l"(b), "l"(acc))
#define PACKB(d, s) \
    asm("mov.b64 %0, {%1, %1};" : "=l"(d) : "f"(s))
#define PACK2(d, lo, hi) \
    asm("mov.b64 %0, {%1, %2};" : "=l"(d) : "f"(lo), "f"(hi))
#define UNPACK2(lo, hi, s) \
    asm("mov.b64 {%0, %1}, %2;" : "=f"(lo), "=f"(hi) : "l"(s))

// cp.async primitives
__device__ __forceinline__ void cp4(uint32_t dst, const float* src, bool ok) {
    int sz = ok ? 4 : 0;
    asm volatile("cp.async.ca.shared.global [%0], [%1], 4, %2;"
                 :: "r"(dst), "l"(src), "r"(sz));
}
__device__ __forceinline__ void cp16(uint32_t dst, const float* src) {
    asm volatile("cp.async.cg.shared.global [%0], [%1], 16;"
                 :: "r"(dst), "l"(src));
}
#define CP_COMMIT() asm volatile("cp.async.commit_group;")
#define CP_WAIT(N) asm volatile("cp.async.wait_group %0;" :: "n"(N))

// 16B-chunk XOR swizzle: kills 2-way smem phase conflicts for 32B-strided lanes
__device__ __forceinline__ int swz(int c) { return c ^ ((c >> 3) & 3); }
__device__ __forceinline__ int swzf(int p) { return (swz(p >> 2) << 2) | (p & 3); }

// ---------------- device scratch (no allocation allowed) ----------------
__device__ float g_x1[BSZ * 64 * TLEN];
__device__ float g_x2[BSZ * 128 * TLEN];
__device__ float g_x3[BSZ * 256 * TLEN];
__device__ float g_x4[BSZ * 512 * TLEN];
__device__ float g_x5[BSZ * 512 * TLEN];
__device__ float g_zqT[BSZ * 512 * TLEN];          // z_q in [b][d][t] layout
__device__ float g_w2T[64 * 5 * 128];
__device__ float g_w3T[128 * 5 * 256];
__device__ float g_w4T[256 * 3 * 512];
__device__ float g_w5T[512 * 3 * 512];
__device__ float g_hwT[512 * 256];                 // head weights [d][h*64+v]
__device__ float g_cnorm[8 * 1024];                // codebook norms
__device__ float g_part[2048];                     // vq-loss partials (32*8*8)

// Output packing offsets (float32 concat of (a_tokens, b_logits, vq_loss))
#define OFF_A 0
#define OFF_B (BSZ * 8 * TLEN)                     // 262144
#define OFF_L (OFF_B + BSZ * 4 * TLEN * 64)        // 8650752

// ---------------- fused weight prep + codebook norms (single launch) -------
__device__ __forceinline__ void tr_seg(int local, const float* __restrict__ w,
                                       float* __restrict__ wT,
                                       int CIN, int COUT, int K) {
    int co = local % COUT;
    int j = (local / COUT) % K;
    int ci = local / (COUT * K);
    wT[local] = w[((size_t)co * CIN + ci) * K + j];
}

#define N_W2 (64 * 5 * 128)
#define N_W3 (128 * 5 * 256)
#define N_W4 (256 * 3 * 512)
#define N_W5 (512 * 3 * 512)
#define N_HW (512 * 256)
#define N_CN (8 * 1024)
#define N_PREP (N_W2 + N_W3 + N_W4 + N_W5 + N_HW + N_CN)

__global__ void prep_kernel(const float* __restrict__ w2, const float* __restrict__ w3,
                            const float* __restrict__ w4, const float* __restrict__ w5,
                            const float* __restrict__ hw, const float* __restrict__ cbk,
                            float* __restrict__ w2T, float* __restrict__ w3T,
                            float* __restrict__ w4T, float* __restrict__ w5T,
                            float* __restrict__ hwT, float* __restrict__ cnorm) {
    int i = blockIdx.x * 256 + threadIdx.x;
    if (i < N_W2) { tr_seg(i, w2, w2T, 64, 128, 5); return; }
    i -= N_W2;
    if (i < N_W3) { tr_seg(i, w3, w3T, 128, 256, 5); return; }
    i -= N_W3;
    if (i < N_W4) { tr_seg(i, w4, w4T, 256, 512, 3); return; }
    i -= N_W4;
    if (i < N_W5) { tr_seg(i, w5, w5T, 512, 512, 3); return; }
    i -= N_W5;
    if (i < N_HW) {
        int co = i % 256;       // h*64+v
        int d = i / 256;
        int h = co >> 6, v = co & 63;
        hwT[i] = hw[((size_t)h * 512 + d) * 64 + v];
        return;
    }
    i -= N_HW;
    if (i < N_CN) {
        // serial ascending-d fp32 sum, matches in-kernel order used before
        const float* row = cbk + (size_t)i * 64;
        float s = 0.f;
#pragma unroll 8
        for (int d = 0; d < 64; d++) { float v = row[d]; s += v * v; }
        cnorm[i] = s;
    }
}

// ---------------- conv1: Cin=1, k=7, ELU ----------------
__global__ void conv1_kernel(const float* __restrict__ audio,
                             const float* __restrict__ w1,
                             const float* __restrict__ b1,
                             float* __restrict__ y) {
    __shared__ float sx[128 + 6];
    __shared__ float sw[64 * 7];
    __shared__ float sb[64];
    const int b = blockIdx.y;
    const int t0 = blockIdx.x * 128;
    const int tid = threadIdx.x;

    for (int i = tid; i < 134; i += 128) {
        int t = t0 - 6 + i;
        sx[i] = (t >= 0) ? audio[(size_t)b * TLEN + t] : 0.f;
    }
    for (int i = tid; i < 448; i += 128) sw[i] = w1[i];
    if (tid < 64) sb[tid] = b1[tid];
    __syncthreads();

    float xv[7];
#pragma unroll
    for (int j = 0; j < 7; j++) xv[j] = sx[tid + j];

    for (int c = 0; c < 64; c++) {
        float acc = sb[c];
#pragma unroll
        for (int j = 0; j < 7; j++) acc += sw[c * 7 + j] * xv[j];
        acc = acc > 0.f ? acc : expm1f(acc);
        y[((size_t)b * 64 + c) * TLEN + t0 + tid] = acc;
    }
}

// ------- conv-as-GEMM, 128x128 tile, 8x8, f32x2, cp.async double-buffer ----
// x: [B][CIN][T], wT: [CIN*K][COUT], y: conv -> [B][COUT][T]; HEAD -> bhtv
template <int CIN, int COUT, int K, int CI_CHUNK, int ELU, int HEAD>
__global__ __launch_bounds__(256, 2)
void conv_gemm(const float* __restrict__ x, const float* __restrict__ wT,
               const float* __restrict__ bias, float* __restrict__ y) {
    constexpr int TT = 128;
    constexpr int CO_TILE = 128;
    constexpr int XROW = 136;                    // halo K-1<=6, swizzle-safe
    constexpr int NX = 8 + K - 1;
    constexpr int NXF4 = (NX + 3) / 4;
    constexpr int XS_FL = CI_CHUNK * XROW;
    constexpr int WS_FL = CI_CHUNK * K * CO_TILE;
    constexpr int NCHUNK = CIN / CI_CHUNK;

    extern __shared__ float smem[];
    float* xs = smem;                 // [2][XS_FL]
    float* ws = smem + 2 * XS_FL;     // [2][WS_FL]
    const uint32_t sb = (uint32_t)__cvta_generic_to_shared(smem);

    const int b = blockIdx.z;
    const int t0 = blockIdx.x * TT;
    const int co0 = blockIdx.y * CO_TILE;
    const int tid = threadIdx.x;
    const int tx = tid & 15;      // t groups
    const int ty = tid >> 4;      // co groups
    const int tb = tx * 8;
    const int cb = ty * 8;

    auto load_chunk = [&](int ci0, int bi) {
        uint32_t xbB = sb + (uint32_t)(bi * XS_FL) * 4u;
        for (int i = tid; i < XS_FL; i += 256) {
            int cc = i / XROW, p = i % XROW;
            int t = t0 - (K - 1) + p;
            bool ok = (t >= 0) && (t < TLEN);
            const float* src = x + ((size_t)b * CIN + ci0 + cc) * TLEN + (ok ? t : 0);
            cp4(xbB + (uint32_t)(cc * XROW + swzf(p)) * 4u, src, ok);
        }
        uint32_t wbB = sb + (uint32_t)(2 * XS_FL + bi * WS_FL) * 4u;
        for (int i4 = tid * 4; i4 < WS_FL; i4 += 1024) {
            int cc = i4 / (K * CO_TILE);
            int rem = i4 % (K * CO_TILE);
            int j = rem / CO_TILE;
            int co = rem % CO_TILE;
            cp16(wbB + (uint32_t)i4 * 4u,
                 wT + ((size_t)(ci0 + cc) * K + j) * COUT + co0 + co);
        }
        CP_COMMIT();
    };

    load_chunk(0, 0);

    ull acc2[4][8];               // pairs over co: (cb+2rp, cb+2rp+1) x 8 t
#pragma unroll
    for (int rp = 0; rp < 4; rp++) {
        ull bb2;
        PACK2(bb2, bias[co0 + cb + 2 * rp], bias[co0 + cb + 2 * rp + 1]);
#pragma unroll
        for (int lt = 0; lt < 8; lt++) acc2[rp][lt] = bb2;
    }

#pragma unroll 1
    for (int c = 0; c < NCHUNK; c++) {
        const int bi = c & 1;
        if (c + 1 < NCHUNK) {
            load_chunk((c + 1) * CI_CHUNK, bi ^ 1);
            CP_WAIT(1);
        } else {
            CP_WAIT(0);
        }
        __syncthreads();

        const float* xsb = xs + bi * XS_FL;
        const float* wsb = ws + bi * WS_FL;
#pragma unroll 1
        for (int cc = 0; cc < CI_CHUNK; cc++) {
            const float* xrow = xsb + cc * XROW;
            float xv[NXF4 * 4];
#pragma unroll
            for (int q = 0; q < NXF4; q++)
                *(float4*)&xv[q * 4] = *(const float4*)&xrow[swz(tx * 2 + q) << 2];
            ull xb[NX];
#pragma unroll
            for (int p = 0; p < NX; p++) PACKB(xb[p], xv[p]);
#pragma unroll
            for (int j = 0; j < K; j++) {
                const float* wrow = wsb + (cc * K + j) * CO_TILE + cb;
                ulonglong2 w01 = *(const ulonglong2*)&wrow[0];
                ulonglong2 w23 = *(const ulonglong2*)&wrow[4];
                ull wp[4] = {w01.x, w01.y, w23.x, w23.y};
#pragma unroll
                for (int rp = 0; rp < 4; rp++)
#pragma unroll
                    for (int lt = 0; lt < 8; lt++)
                        FMA2(acc2[rp][lt], wp[rp], xb[lt + j]);
            }
        }
        __syncthreads();
    }

    // unpack accumulators
    float accs[8][8];
#pragma unroll
    for (int rp = 0; rp < 4; rp++)
#pragma unroll
        for (int lt = 0; lt < 8; lt++)
            UNPACK2(accs[2 * rp][lt], accs[2 * rp + 1][lt], acc2[rp][lt]);

    if (HEAD) {
        // co = h*64 + v; each thread's 8 co stay within one head (8 | 64)
        const int h = (co0 + cb) >> 6;
        const int v0 = (co0 + cb) & 63;
#pragma unroll
        for (int lt = 0; lt < 8; lt++) {
            int t = t0 + tb + lt;
            float4 o0 = make_float4(accs[0][lt], accs[1][lt], accs[2][lt], accs[3][lt]);
            float4 o1 = make_float4(accs[4][lt], accs[5][lt], accs[6][lt], accs[7][lt]);
            float* base = &y[(((size_t)b * 4 + h) * TLEN + t) * 64 + v0];
            *(float4*)base = o0;
            *(float4*)(base + 4) = o1;
        }
    } else {
#pragma unroll
        for (int r = 0; r < 8; r++) {
            float o[8];
#pragma unroll
            for (int lt = 0; lt < 8; lt++) {
                float a = accs[r][lt];
                if (ELU) a = a > 0.f ? a : expm1f(a);
                o[lt] = a;
            }
            float* base = &y[((size_t)b * COUT + co0 + cb + r) * TLEN + t0 + tb];
            *(float4*)base = *(float4*)&o[0];
            *(float4*)(base + 4) = *(float4*)&o[4];
        }
    }
}

// ---------------- VQ: dist-GEMM + argmin + gather + loss, pipelined --------
// 256 thr, tile 128 tokens x 128 codes (8 chunks), cp.async double buffer
#define VQ_ZT 0                       // 8192 floats [64][128] swizzled
#define VQ_CB0 8192                   // 8448 floats [64][132]
#define VQ_CB1 (8192 + 8448)          // 8448 floats
#define VQ_CNORM (8192 + 16896)       // 1024 floats
#define VQ_ZN (VQ_CNORM + 1024)       // 128 floats
#define VQ_BI (VQ_ZN + 128)           // 128 ints
#define VQ_FLOATS (VQ_BI + 128)       // 26368
#define VQ_BYTES (VQ_FLOATS * 4)      // 105472
// aliases into dead regions:
#define VQ_RV VQ_CB0                  // 2048 floats (after chunk loop)
#define VQ_RI (VQ_CB0 + 2048)         // 2048 ints
#define VQ_QS VQ_CB0                  // 8448 floats (after argmin)
#define VQ_LS VQ_CNORM                // 256 floats (after chunk loop)

__global__ __launch_bounds__(256, 2)
void vq_kernel(const float* __restrict__ x5, const float* __restrict__ cbk,
               const float* __restrict__ cnormG,
               float* __restrict__ zqT, float* __restrict__ out_a,
               float* __restrict__ partial) {
    extern __shared__ float smem[];
    const uint32_t sb = (uint32_t)__cvta_generic_to_shared(smem);
    float* ztT = smem + VQ_ZT;
    float* cnormS = smem + VQ_CNORM;
    float* znorm = smem + VQ_ZN;
    int* besti = (int*)(smem + VQ_BI);
    float* redv = smem + VQ_RV;
    int* redi = (int*)(smem + VQ_RI);
    float* qs = smem + VQ_QS;
    float* lscr = smem + VQ_LS;

    const int b = blockIdx.z, g = blockIdx.y;
    const int t0 = blockIdx.x * 128;
    const int tid = threadIdx.x;
    const int tx = tid & 15;          // token groups
    const int ty = tid >> 4;          // code groups
    const int trow = tx * 8;          // 8 tokens per thread
    const int cbase = ty * 8;         // 8 codes per thread (within chunk)

    // group0: ztT + cnormS + codebook chunk 0
    for (int i = tid; i < 8192; i += 256) {
        int d = i >> 7, lt = i & 127;
        cp4(sb + (uint32_t)(VQ_ZT + d * 128 + swzf(lt)) * 4u,
            x5 + (((size_t)b * 512) + (g << 6) + d) * TLEN + t0 + lt, true);
    }
    cp16(sb + (uint32_t)(VQ_CNORM + tid * 4) * 4u, cnormG + g * 1024 + tid * 4);
    for (int i = tid; i < 8192; i += 256) {
        int kk = i >> 6, d = i & 63;
        cp4(sb + (uint32_t)(VQ_CB0 + d * 132 + kk) * 4u,
            cbk + ((size_t)g * 1024 + kk) * 64 + d, true);
    }
    CP_COMMIT();

    float zn[8];
    float bv[8];
    int bi8[8];
#pragma unroll
    for (int a = 0; a < 8; a++) { bv[a] = 3.4e38f; bi8[a] = 0; }

#pragma unroll 1
    for (int c = 0; c < 8; c++) {
        const int k0 = c << 7;
        if (c + 1 < 8) {
            const int koff = (c + 1) << 7;
            uint32_t cbB = sb + (uint32_t)(((c + 1) & 1) ? VQ_CB1 : VQ_CB0) * 4u;
            for (int i = tid; i < 8192; i += 256) {
                int kk = i >> 6, d = i & 63;
                cp4(cbB + (uint32_t)(d * 132 + kk) * 4u,
                    cbk + ((size_t)g * 1024 + koff + kk) * 64 + d, true);
            }
            CP_COMMIT();
            CP_WAIT(1);
        } else {
            CP_WAIT(0);
        }
        __syncthreads();

        if (c == 0) {
            if (tid < 128) {
                float s = 0.f;
                int off = swzf(tid);
#pragma unroll 8
                for (int d = 0; d < 64; d++) { float v = ztT[d * 128 + off]; s += v * v; }
                znorm[tid] = s;
            }
            __syncthreads();
#pragma unroll
            for (int a = 0; a < 8; a++) zn[a] = znorm[trow + a];
        }

        const float* ct = smem + ((c & 1) ? VQ_CB1 : VQ_CB0);

        ull acc2[8][4];    // pairs over code: (cbase+2q, cbase+2q+1)
#pragma unroll
        for (int a = 0; a < 8; a++)
#pragma unroll
            for (int q = 0; q < 4; q++) acc2[a][q] = 0ull;

#pragma unroll 4
        for (int d = 0; d < 64; d++) {
            float zz[8];
            *(float4*)&zz[0] = *(const float4*)&ztT[d * 128 + (swz(tx * 2) << 2)];
            *(float4*)&zz[4] = *(const float4*)&ztT[d * 128 + (swz(tx * 2 + 1) << 2)];
            ull zb[8];
#pragma unroll
            for (int a = 0; a < 8; a++) PACKB(zb[a], zz[a]);
            ulonglong2 c01 = *(const ulonglong2*)&ct[d * 132 + cbase];
            ulonglong2 c23 = *(const ulonglong2*)&ct[d * 132 + cbase + 4];
            ull cp_[4] = {c01.x, c01.y, c23.x, c23.y};
#pragma unroll
            for (int a = 0; a < 8; a++)
#pragma unroll
                for (int q = 0; q < 4; q++)
                    FMA2(acc2[a][q], zb[a], cp_[q]);
        }

        float accs[8][8];
#pragma unroll
        for (int a = 0; a < 8; a++)
#pragma unroll
            for (int q = 0; q < 4; q++)
                UNPACK2(accs[a][2 * q], accs[a][2 * q + 1], acc2[a][q]);

        float cn[8];
#pragma unroll
        for (int cc = 0; cc < 8; cc++) cn[cc] = cnormS[k0 + cbase + cc];
#pragma unroll
        for (int a = 0; a < 8; a++) {
#pragma unroll
            for (int cc = 0; cc < 8; cc++) {
                float dist = zn[a] + cn[cc] - 2.f * accs[a][cc];
                int idx = k0 + cbase + cc;
                if (dist < bv[a]) { bv[a] = dist; bi8[a] = idx; }  // strict <
            }
        }
        __syncthreads();
    }

    // cross-thread argmin reduction (16 contributors per token); redv aliases CB0
#pragma unroll
    for (int a = 0; a < 8; a++) {
        int tok = trow + a;
        redv[tok * 16 + ty] = bv[a];
        redi[tok * 16 + ty] = bi8[a];
    }
    __syncthreads();
    if (tid < 128) {
        float best = redv[tid * 16];
        int bidx = redi[tid * 16];
#pragma unroll
        for (int s = 1; s < 16; s++) {
            float v = redv[tid * 16 + s];
            int ii = redi[tid * 16 + s];
            if (v < best || (v == best && ii < bidx)) { best = v; bidx = ii; }
        }
        besti[tid] = bidx;
        out_a[((size_t)b * 8 + g) * TLEN + t0 + tid] = (float)bidx;
    }
    __syncthreads();

    // gather q (coalesced codebook reads), exact loss, stage q for coalesced store
    float ls = 0.f;
    for (int i = tid; i < 64 * 128; i += 256) {
        int d = i & 63, lt = i >> 6;
        float qv = cbk[((size_t)g * 1024 + besti[lt]) * 64 + d];
        float df = qv - ztT[d * 128 + swzf(lt)];
        ls += df * df;
        qs[d * 132 + lt] = qv;
    }
    __syncthreads();
    for (int i = tid; i < 64 * 128; i += 256) {
        int lt = i & 127, d = i >> 7;
        zqT[(((size_t)b * 512) + (g << 6) + d) * TLEN + t0 + lt] = qs[d * 132 + lt];
    }

    // deterministic block loss reduction (lscr aliases cnorm region, now dead)
    lscr[tid] = ls;
    __syncthreads();
    for (int s = 128; s > 0; s >>= 1) {
        if (tid < s) lscr[tid] += lscr[tid + s];
        __syncthreads();
    }
    if (tid == 0)
        partial[((size_t)b * 8 + g) * 32 + blockIdx.x] = lscr[0];
}

// ---------------- final deterministic loss sum ----------------
__global__ void loss_kernel(const float* __restrict__ partial, float* __restrict__ out) {
    __shared__ float s[256];
    int tid = threadIdx.x;
    float v = 0.f;
    for (int i = tid; i < 2048; i += 256) v += partial[i];
    s[tid] = v;
    __syncthreads();
    for (int k = 128; k > 0; k >>= 1) {
        if (tid < k) s[tid] += s[tid + k];
        __syncthreads();
    }
    if (tid == 0) out[OFF_L] = s[0] * (1.f / (8.f * 4096.f * 64.f));
}

// ---------------- launch ----------------
extern "C" void kernel_launch(void* const* d_in, const int* in_sizes, int n_in,
                              void* d_out, int out_size) {
    const float* audio = (const float*)d_in[0];
    const float* w1 = (const float*)d_in[1];
    const float* b1 = (const float*)d_in[2];
    const float* w2 = (const float*)d_in[3];
    const float* b2 = (const float*)d_in[4];
    const float* w3 = (const float*)d_in[5];
    const float* b3 = (const float*)d_in[6];
    const float* w4 = (const float*)d_in[7];
    const float* b4 = (const float*)d_in[8];
    const float* w5 = (const float*)d_in[9];
    const float* b5 = (const float*)d_in[10];
    const float* codebooks = (const float*)d_in[11];
    const float* head_w = (const float*)d_in[12];
    const float* head_b = (const float*)d_in[13];
    float* out = (float*)d_out;

    float *x1, *x2, *x3, *x4, *x5, *zqT, *w2T, *w3T, *w4T, *w5T, *hwT, *cnm, *part;
    cudaGetSymbolAddress((void**)&x1, g_x1);
    cudaGetSymbolAddress((void**)&x2, g_x2);
    cudaGetSymbolAddress((void**)&x3, g_x3);
    cudaGetSymbolAddress((void**)&x4, g_x4);
    cudaGetSymbolAddress((void**)&x5, g_x5);
    cudaGetSymbolAddress((void**)&zqT, g_zqT);
    cudaGetSymbolAddress((void**)&w2T, g_w2T);
    cudaGetSymbolAddress((void**)&w3T, g_w3T);
    cudaGetSymbolAddress((void**)&w4T, g_w4T);
    cudaGetSymbolAddress((void**)&w5T, g_w5T);
    cudaGetSymbolAddress((void**)&hwT, g_hwT);
    cudaGetSymbolAddress((void**)&cnm, g_cnorm);
    cudaGetSymbolAddress((void**)&part, g_part);

    // dynamic smem sizes (bytes): 2*(CI_CHUNK*136 + CI_CHUNK*K*128)*4
    const int SM_C2 = (2 * (8 * 136) + 2 * (8 * 5 * 128)) * 4;      // 49664
    const int SM_C3 = SM_C2;                                        // 49664
    const int SM_C4 = (2 * (16 * 136) + 2 * (16 * 3 * 128)) * 4;    // 66560
    const int SM_C5 = SM_C4;                                        // 66560
    const int SM_HD = (2 * (16 * 136) + 2 * (16 * 1 * 128)) * 4;    // 33792

    cudaFuncSetAttribute((const void*)conv_gemm<64, 128, 5, 8, 1, 0>,
                         cudaFuncAttributeMaxDynamicSharedMemorySize, SM_C2);
    cudaFuncSetAttribute((const void*)conv_gemm<128, 256, 5, 8, 1, 0>,
                         cudaFuncAttributeMaxDynamicSharedMemorySize, SM_C3);
    cudaFuncSetAttribute((const void*)conv_gemm<256, 512, 3, 16, 1, 0>,
                         cudaFuncAttributeMaxDynamicSharedMemorySize, SM_C4);
    cudaFuncSetAttribute((const void*)conv_gemm<512, 512, 3, 16, 0, 0>,
                         cudaFuncAttributeMaxDynamicSharedMemorySize, SM_C5);
    cudaFuncSetAttribute((const void*)conv_gemm<512, 256, 1, 16, 0, 1>,
                         cudaFuncAttributeMaxDynamicSharedMemorySize, SM_HD);
    cudaFuncSetAttribute((const void*)vq_kernel,
                         cudaFuncAttributeMaxDynamicSharedMemorySize, VQ_BYTES);

    // fused weight prep + codebook norms (1 launch)
    prep_kernel<<<(N_PREP + 255) / 256, 256>>>(w2, w3, w4, w5, head_w, codebooks,
                                               w2T, w3T, w4T, w5T, hwT, cnm);

    // encoder
    conv1_kernel<<<dim3(32, 8), 128>>>(audio, w1, b1, x1);
    conv_gemm<64, 128, 5, 8, 1, 0><<<dim3(32, 1, 8), 256, SM_C2>>>(x1, w2T, b2, x2);
    conv_gemm<128, 256, 5, 8, 1, 0><<<dim3(32, 2, 8), 256, SM_C3>>>(x2, w3T, b3, x3);
    conv_gemm<256, 512, 3, 16, 1, 0><<<dim3(32, 4, 8), 256, SM_C4>>>(x3, w4T, b4, x4);
    conv_gemm<512, 512, 3, 16, 0, 0><<<dim3(32, 4, 8), 256, SM_C5>>>(x4, w5T, b5, x5);

    // VQ + heads + loss
    vq_kernel<<<dim3(32, 8, 8), 256, VQ_BYTES>>>(x5, codebooks, cnm,
                                                 zqT, out + OFF_A, part);
    conv_gemm<512, 256, 1, 16, 0, 1><<<dim3(32, 2, 8), 256, SM_HD>>>(zqT, hwT, head_b,
                                                                     out + OFF_B);
    loss_kernel<<<1, 256>>>(part, out);
}

// round 5
// speedup vs baseline: 1.3239x; 1.0084x over previous
#include <cuda_runtime.h>
#include <math.h>
#include <stdint.h>

// Problem constants
#define TLEN 4096
#define BSZ 8

typedef unsigned long long ull;

// Packed fp32x2 helpers (Blackwell sm_100a+): full-rate fp32 FMA
#define FMA2(acc, a, b) \
    asm("fma.rn.f32x2 %0, %1, %2, %3;" : "=l"(acc) : "l"(a), "l"(b), "l"(acc))
#define PACKB(d, s) \
    asm("mov.b64 %0, {%1, %1};" : "=l"(d) : "f"(s))
#define PACK2(d, lo, hi) \
    asm("mov.b64 %0, {%1, %2};" : "=l"(d) : "f"(lo), "f"(hi))
#define UNPACK2(lo, hi, s) \
    asm("mov.b64 {%0, %1}, %2;" : "=f"(lo), "=f"(hi) : "l"(s))

// cp.async primitives
__device__ __forceinline__ void cp4(uint32_t dst, const float* src, bool ok) {
    int sz = ok ? 4 : 0;
    asm volatile("cp.async.ca.shared.global [%0], [%1], 4, %2;"
                 :: "r"(dst), "l"(src), "r"(sz));
}
__device__ __forceinline__ void cp16(uint32_t dst, const float* src) {
    asm volatile("cp.async.cg.shared.global [%0], [%1], 16;"
                 :: "r"(dst), "l"(src));
}
#define CP_COMMIT() asm volatile("cp.async.commit_group;")
#define CP_WAIT(N) asm volatile("cp.async.wait_group %0;" :: "n"(N))

// 16B-chunk XOR swizzle: kills 2-way smem phase conflicts for 32B-strided lanes
__device__ __forceinline__ int swz(int c) { return c ^ ((c >> 3) & 3); }
__device__ __forceinline__ int swzf(int p) { return (swz(p >> 2) << 2) | (p & 3); }

// ---------------- device scratch (no allocation allowed) ----------------
__device__ float g_x1[BSZ * 64 * TLEN];
__device__ float g_x2[BSZ * 128 * TLEN];
__device__ float g_x3[BSZ * 256 * TLEN];
__device__ float g_x4[BSZ * 512 * TLEN];
__device__ float g_x5[BSZ * 512 * TLEN];
__device__ float g_zqT[BSZ * 512 * TLEN];          // z_q in [b][d][t] layout
__device__ float g_w2T[64 * 5 * 128];
__device__ float g_w3T[128 * 5 * 256];
__device__ float g_w4T[256 * 3 * 512];
__device__ float g_w5T[512 * 3 * 512];
__device__ float g_hwT[512 * 256];                 // head weights [d][h*64+v]
__device__ float g_cnorm[8 * 1024];                // codebook norms
__device__ float g_part[2048];                     // vq-loss partials (32*8*8)

// Output packing offsets (float32 concat of (a_tokens, b_logits, vq_loss))
#define OFF_A 0
#define OFF_B (BSZ * 8 * TLEN)                     // 262144
#define OFF_L (OFF_B + BSZ * 4 * TLEN * 64)        // 8650752

// ---------------- fused weight prep + codebook norms (single launch) -------
__device__ __forceinline__ void tr_seg(int local, const float* __restrict__ w,
                                       float* __restrict__ wT,
                                       int CIN, int COUT, int K) {
    int co = local % COUT;
    int j = (local / COUT) % K;
    int ci = local / (COUT * K);
    wT[local] = w[((size_t)co * CIN + ci) * K + j];
}

#define N_W2 (64 * 5 * 128)
#define N_W3 (128 * 5 * 256)
#define N_W4 (256 * 3 * 512)
#define N_W5 (512 * 3 * 512)
#define N_HW (512 * 256)
#define N_CN (8 * 1024)
#define N_PREP (N_W2 + N_W3 + N_W4 + N_W5 + N_HW + N_CN)

__global__ void prep_kernel(const float* __restrict__ w2, const float* __restrict__ w3,
                            const float* __restrict__ w4, const float* __restrict__ w5,
                            const float* __restrict__ hw, const float* __restrict__ cbk,
                            float* __restrict__ w2T, float* __restrict__ w3T,
                            float* __restrict__ w4T, float* __restrict__ w5T,
                            float* __restrict__ hwT, float* __restrict__ cnorm) {
    int i = blockIdx.x * 256 + threadIdx.x;
    if (i < N_W2) { tr_seg(i, w2, w2T, 64, 128, 5); return; }
    i -= N_W2;
    if (i < N_W3) { tr_seg(i, w3, w3T, 128, 256, 5); return; }
    i -= N_W3;
    if (i < N_W4) { tr_seg(i, w4, w4T, 256, 512, 3); return; }
    i -= N_W4;
    if (i < N_W5) { tr_seg(i, w5, w5T, 512, 512, 3); return; }
    i -= N_W5;
    if (i < N_HW) {
        int co = i % 256;       // h*64+v
        int d = i / 256;
        int h = co >> 6, v = co & 63;
        hwT[i] = hw[((size_t)h * 512 + d) * 64 + v];
        return;
    }
    i -= N_HW;
    if (i < N_CN) {
        // serial ascending-d fp32 sum, matches in-kernel order used before
        const float* row = cbk + (size_t)i * 64;
        float s = 0.f;
#pragma unroll 8
        for (int d = 0; d < 64; d++) { float v = row[d]; s += v * v; }
        cnorm[i] = s;
    }
}

// ---------------- conv1: Cin=1, k=7, ELU ----------------
__global__ void conv1_kernel(const float* __restrict__ audio,
                             const float* __restrict__ w1,
                             const float* __restrict__ b1,
                             float* __restrict__ y) {
    __shared__ float sx[128 + 6];
    __shared__ float sw[64 * 7];
    __shared__ float sb[64];
    const int b = blockIdx.y;
    const int t0 = blockIdx.x * 128;
    const int tid = threadIdx.x;

    for (int i = tid; i < 134; i += 128) {
        int t = t0 - 6 + i;
        sx[i] = (t >= 0) ? audio[(size_t)b * TLEN + t] : 0.f;
    }
    for (int i = tid; i < 448; i += 128) sw[i] = w1[i];
    if (tid < 64) sb[tid] = b1[tid];
    __syncthreads();

    float xv[7];
#pragma unroll
    for (int j = 0; j < 7; j++) xv[j] = sx[tid + j];

    for (int c = 0; c < 64; c++) {
        float acc = sb[c];
#pragma unroll
        for (int j = 0; j < 7; j++) acc += sw[c * 7 + j] * xv[j];
        acc = acc > 0.f ? acc : expm1f(acc);
        y[((size_t)b * 64 + c) * TLEN + t0 + tid] = acc;
    }
}

// --- conv-as-GEMM, 128x128 tile, 8x8, f32x2, 3-stage cp.async, 1 sync/chunk
// x: [B][CIN][T], wT: [CIN*K][COUT], y: conv -> [B][COUT][T]; HEAD -> bhtv
template <int CIN, int COUT, int K, int CI_CHUNK, int ELU, int HEAD>
__global__ __launch_bounds__(256, 2)
void conv_gemm(const float* __restrict__ x, const float* __restrict__ wT,
               const float* __restrict__ bias, float* __restrict__ y) {
    constexpr int TT = 128;
    constexpr int CO_TILE = 128;
    constexpr int XROW = 136;                    // halo K-1<=6, swizzle-safe
    constexpr int NX = 8 + K - 1;
    constexpr int NXF4 = (NX + 3) / 4;
    constexpr int XS_FL = CI_CHUNK * XROW;
    constexpr int WS_FL = CI_CHUNK * K * CO_TILE;
    constexpr int STG_FL = XS_FL + WS_FL;        // one pipeline stage
    constexpr int NCHUNK = CIN / CI_CHUNK;

    extern __shared__ float smem[];
    const uint32_t sb = (uint32_t)__cvta_generic_to_shared(smem);

    const int b = blockIdx.z;
    const int t0 = blockIdx.x * TT;
    const int co0 = blockIdx.y * CO_TILE;
    const int tid = threadIdx.x;
    const int tx = tid & 15;      // t groups
    const int ty = tid >> 4;      // co groups
    const int tb = tx * 8;
    const int cb = ty * 8;

    auto load_chunk = [&](int c, int st) {
        const int ci0 = c * CI_CHUNK;
        uint32_t xbB = sb + (uint32_t)(st * STG_FL) * 4u;
        for (int i = tid; i < XS_FL; i += 256) {
            int cc = i / XROW, p = i % XROW;
            int t = t0 - (K - 1) + p;
            bool ok = (t >= 0) && (t < TLEN);
            const float* src = x + ((size_t)b * CIN + ci0 + cc) * TLEN + (ok ? t : 0);
            cp4(xbB + (uint32_t)(cc * XROW + swzf(p)) * 4u, src, ok);
        }
        uint32_t wbB = xbB + (uint32_t)XS_FL * 4u;
        for (int i4 = tid * 4; i4 < WS_FL; i4 += 1024) {
            int cc = i4 / (K * CO_TILE);
            int rem = i4 % (K * CO_TILE);
            int j = rem / CO_TILE;
            int co = rem % CO_TILE;
            cp16(wbB + (uint32_t)i4 * 4u,
                 wT + ((size_t)(ci0 + cc) * K + j) * COUT + co0 + co);
        }
        CP_COMMIT();
    };

    load_chunk(0, 0);
    if (NCHUNK > 1) load_chunk(1, 1);

    ull acc2[4][8];               // pairs over co: (cb+2rp, cb+2rp+1) x 8 t
#pragma unroll
    for (int rp = 0; rp < 4; rp++) {
        ull bb2;
        PACK2(bb2, bias[co0 + cb + 2 * rp], bias[co0 + cb + 2 * rp + 1]);
#pragma unroll
        for (int lt = 0; lt < 8; lt++) acc2[rp][lt] = bb2;
    }

    int st = 0;                   // stage holding chunk c
#pragma unroll 1
    for (int c = 0; c < NCHUNK; c++) {
        if (c + 1 < NCHUNK) { CP_WAIT(1); } else { CP_WAIT(0); }
        __syncthreads();
        if (c + 2 < NCHUNK) {
            int st2 = st + 2; if (st2 >= 3) st2 -= 3;
            load_chunk(c + 2, st2);
        }

        const float* xsb = smem + st * STG_FL;
        const float* wsb = xsb + XS_FL;
#pragma unroll 1
        for (int cc = 0; cc < CI_CHUNK; cc++) {
            const float* xrow = xsb + cc * XROW;
            float xv[NXF4 * 4];
#pragma unroll
            for (int q = 0; q < NXF4; q++)
                *(float4*)&xv[q * 4] = *(const float4*)&xrow[swz(tx * 2 + q) << 2];
            ull xb[NX];
#pragma unroll
            for (int p = 0; p < NX; p++) PACKB(xb[p], xv[p]);
#pragma unroll
            for (int j = 0; j < K; j++) {
                const float* wrow = wsb + (cc * K + j) * CO_TILE + cb;
                ulonglong2 w01 = *(const ulonglong2*)&wrow[0];
                ulonglong2 w23 = *(const ulonglong2*)&wrow[4];
                ull wp[4] = {w01.x, w01.y, w23.x, w23.y};
#pragma unroll
                for (int rp = 0; rp < 4; rp++)
#pragma unroll
                    for (int lt = 0; lt < 8; lt++)
                        FMA2(acc2[rp][lt], wp[rp], xb[lt + j]);
            }
        }
        if (++st == 3) st = 0;
    }

    // unpack accumulators
    float accs[8][8];
#pragma unroll
    for (int rp = 0; rp < 4; rp++)
#pragma unroll
        for (int lt = 0; lt < 8; lt++)
            UNPACK2(accs[2 * rp][lt], accs[2 * rp + 1][lt], acc2[rp][lt]);

    if (HEAD) {
        // co = h*64 + v; each thread's 8 co stay within one head (8 | 64)
        const int h = (co0 + cb) >> 6;
        const int v0 = (co0 + cb) & 63;
#pragma unroll
        for (int lt = 0; lt < 8; lt++) {
            int t = t0 + tb + lt;
            float4 o0 = make_float4(accs[0][lt], accs[1][lt], accs[2][lt], accs[3][lt]);
            float4 o1 = make_float4(accs[4][lt], accs[5][lt], accs[6][lt], accs[7][lt]);
            float* base = &y[(((size_t)b * 4 + h) * TLEN + t) * 64 + v0];
            *(float4*)base = o0;
            *(float4*)(base + 4) = o1;
        }
    } else {
#pragma unroll
        for (int r = 0; r < 8; r++) {
            float o[8];
#pragma unroll
            for (int lt = 0; lt < 8; lt++) {
                float a = accs[r][lt];
                if (ELU) a = a > 0.f ? a : expm1f(a);
                o[lt] = a;
            }
            float* base = &y[((size_t)b * COUT + co0 + cb + r) * TLEN + t0 + tb];
            *(float4*)base = *(float4*)&o[0];
            *(float4*)(base + 4) = *(float4*)&o[4];
        }
    }
}

// ---------------- VQ: dist-GEMM + argmin + gather + loss, pipelined --------
// 256 thr, tile 128 tokens x 128 codes (8 chunks), cp.async double buffer
#define VQ_ZT 0                       // 8192 floats [64][128] swizzled
#define VQ_CB0 8192                   // 8448 floats [64][132]
#define VQ_CB1 (8192 + 8448)          // 8448 floats
#define VQ_CNORM (8192 + 16896)       // 1024 floats
#define VQ_ZN (VQ_CNORM + 1024)       // 128 floats
#define VQ_BI (VQ_ZN + 128)           // 128 ints
#define VQ_FLOATS (VQ_BI + 128)       // 26368
#define VQ_BYTES (VQ_FLOATS * 4)      // 105472
// aliases into dead regions:
#define VQ_RV VQ_CB0                  // 2048 floats (after chunk loop)
#define VQ_RI (VQ_CB0 + 2048)         // 2048 ints
#define VQ_QS VQ_CB0                  // 8448 floats (after argmin)
#define VQ_LS VQ_CNORM                // 256 floats (after chunk loop)

__global__ __launch_bounds__(256, 2)
void vq_kernel(const float* __restrict__ x5, const float* __restrict__ cbk,
               const float* __restrict__ cnormG,
               float* __restrict__ zqT, float* __restrict__ out_a,
               float* __restrict__ partial) {
    extern __shared__ float smem[];
    const uint32_t sb = (uint32_t)__cvta_generic_to_shared(smem);
    float* ztT = smem + VQ_ZT;
    float* cnormS = smem + VQ_CNORM;
    float* znorm = smem + VQ_ZN;
    int* besti = (int*)(smem + VQ_BI);
    float* redv = smem + VQ_RV;
    int* redi = (int*)(smem + VQ_RI);
    float* qs = smem + VQ_QS;
    float* lscr = smem + VQ_LS;

    const int b = blockIdx.z, g = blockIdx.y;
    const int t0 = blockIdx.x * 128;
    const int tid = threadIdx.x;
    const int tx = tid & 15;          // token groups
    const int ty = tid >> 4;          // code groups
    const int trow = tx * 8;          // 8 tokens per thread
    const int cbase = ty * 8;         // 8 codes per thread (within chunk)

    // group0: ztT + cnormS + codebook chunk 0
    for (int i = tid; i < 8192; i += 256) {
        int d = i >> 7, lt = i & 127;
        cp4(sb + (uint32_t)(VQ_ZT + d * 128 + swzf(lt)) * 4u,
            x5 + (((size_t)b * 512) + (g << 6) + d) * TLEN + t0 + lt, true);
    }
    cp16(sb + (uint32_t)(VQ_CNORM + tid * 4) * 4u, cnormG + g * 1024 + tid * 4);
    for (int i = tid; i < 8192; i += 256) {
        int kk = i >> 6, d = i & 63;
        cp4(sb + (uint32_t)(VQ_CB0 + d * 132 + kk) * 4u,
            cbk + ((size_t)g * 1024 + kk) * 64 + d, true);
    }
    CP_COMMIT();

    float zn[8];
    float bv[8];
    int bi8[8];
#pragma unroll
    for (int a = 0; a < 8; a++) { bv[a] = 3.4e38f; bi8[a] = 0; }

#pragma unroll 1
    for (int c = 0; c < 8; c++) {
        const int k0 = c << 7;
        if (c + 1 < 8) {
            const int koff = (c + 1) << 7;
            uint32_t cbB = sb + (uint32_t)(((c + 1) & 1) ? VQ_CB1 : VQ_CB0) * 4u;
            for (int i = tid; i < 8192; i += 256) {
                int kk = i >> 6, d = i & 63;
                cp4(cbB + (uint32_t)(d * 132 + kk) * 4u,
                    cbk + ((size_t)g * 1024 + koff + kk) * 64 + d, true);
            }
            CP_COMMIT();
            CP_WAIT(1);
        } else {
            CP_WAIT(0);
        }
        __syncthreads();

        if (c == 0) {
            if (tid < 128) {
                float s = 0.f;
                int off = swzf(tid);
#pragma unroll 8
                for (int d = 0; d < 64; d++) { float v = ztT[d * 128 + off]; s += v * v; }
                znorm[tid] = s;
            }
            __syncthreads();
#pragma unroll
            for (int a = 0; a < 8; a++) zn[a] = znorm[trow + a];
        }

        const float* ct = smem + ((c & 1) ? VQ_CB1 : VQ_CB0);

        ull acc2[8][4];    // pairs over code: (cbase+2q, cbase+2q+1)
#pragma unroll
        for (int a = 0; a < 8; a++)
#pragma unroll
            for (int q = 0; q < 4; q++) acc2[a][q] = 0ull;

#pragma unroll 4
        for (int d = 0; d < 64; d++) {
            float zz[8];
            *(float4*)&zz[0] = *(const float4*)&ztT[d * 128 + (swz(tx * 2) << 2)];
            *(float4*)&zz[4] = *(const float4*)&ztT[d * 128 + (swz(tx * 2 + 1) << 2)];
            ull zb[8];
#pragma unroll
            for (int a = 0; a < 8; a++) PACKB(zb[a], zz[a]);
            ulonglong2 c01 = *(const ulonglong2*)&ct[d * 132 + cbase];
            ulonglong2 c23 = *(const ulonglong2*)&ct[d * 132 + cbase + 4];
            ull cp_[4] = {c01.x, c01.y, c23.x, c23.y};
#pragma unroll
            for (int a = 0; a < 8; a++)
#pragma unroll
                for (int q = 0; q < 4; q++)
                    FMA2(acc2[a][q], zb[a], cp_[q]);
        }

        float accs[8][8];
#pragma unroll
        for (int a = 0; a < 8; a++)
#pragma unroll
            for (int q = 0; q < 4; q++)
                UNPACK2(accs[a][2 * q], accs[a][2 * q + 1], acc2[a][q]);

        float cn[8];
#pragma unroll
        for (int cc = 0; cc < 8; cc++) cn[cc] = cnormS[k0 + cbase + cc];
#pragma unroll
        for (int a = 0; a < 8; a++) {
#pragma unroll
            for (int cc = 0; cc < 8; cc++) {
                float dist = zn[a] + cn[cc] - 2.f * accs[a][cc];
                int idx = k0 + cbase + cc;
                if (dist < bv[a]) { bv[a] = dist; bi8[a] = idx; }  // strict <
            }
        }
        __syncthreads();
    }

    // cross-thread argmin reduction (16 contributors per token); redv aliases CB0
#pragma unroll
    for (int a = 0; a < 8; a++) {
        int tok = trow + a;
        redv[tok * 16 + ty] = bv[a];
        redi[tok * 16 + ty] = bi8[a];
    }
    __syncthreads();
    if (tid < 128) {
        float best = redv[tid * 16];
        int bidx = redi[tid * 16];
#pragma unroll
        for (int s = 1; s < 16; s++) {
            float v = redv[tid * 16 + s];
            int ii = redi[tid * 16 + s];
            if (v < best || (v == best && ii < bidx)) { best = v; bidx = ii; }
        }
        besti[tid] = bidx;
        out_a[((size_t)b * 8 + g) * TLEN + t0 + tid] = (float)bidx;
    }
    __syncthreads();

    // gather q (coalesced codebook reads), exact loss, stage q for coalesced store
    float ls = 0.f;
    for (int i = tid; i < 64 * 128; i += 256) {
        int d = i & 63, lt = i >> 6;
        float qv = cbk[((size_t)g * 1024 + besti[lt]) * 64 + d];
        float df = qv - ztT[d * 128 + swzf(lt)];
        ls += df * df;
        qs[d * 132 + lt] = qv;
    }
    __syncthreads();
    for (int i = tid; i < 64 * 128; i += 256) {
        int lt = i & 127, d = i >> 7;
        zqT[(((size_t)b * 512) + (g << 6) + d) * TLEN + t0 + lt] = qs[d * 132 + lt];
    }

    // deterministic block loss reduction (lscr aliases cnorm region, now dead)
    lscr[tid] = ls;
    __syncthreads();
    for (int s = 128; s > 0; s >>= 1) {
        if (tid < s) lscr[tid] += lscr[tid + s];
        __syncthreads();
    }
    if (tid == 0)
        partial[((size_t)b * 8 + g) * 32 + blockIdx.x] = lscr[0];
}

// ---------------- final deterministic loss sum ----------------
__global__ void loss_kernel(const float* __restrict__ partial, float* __restrict__ out) {
    __shared__ float s[256];
    int tid = threadIdx.x;
    float v = 0.f;
    for (int i = tid; i < 2048; i += 256) v += partial[i];
    s[tid] = v;
    __syncthreads();
    for (int k = 128; k > 0; k >>= 1) {
        if (tid < k) s[tid] += s[tid + k];
        __syncthreads();
    }
    if (tid == 0) out[OFF_L] = s[0] * (1.f / (8.f * 4096.f * 64.f));
}

// ---------------- launch ----------------
extern "C" void kernel_launch(void* const* d_in, const int* in_sizes, int n_in,
                              void* d_out, int out_size) {
    const float* audio = (const float*)d_in[0];
    const float* w1 = (const float*)d_in[1];
    const float* b1 = (const float*)d_in[2];
    const float* w2 = (const float*)d_in[3];
    const float* b2 = (const float*)d_in[4];
    const float* w3 = (const float*)d_in[5];
    const float* b3 = (const float*)d_in[6];
    const float* w4 = (const float*)d_in[7];
    const float* b4 = (const float*)d_in[8];
    const float* w5 = (const float*)d_in[9];
    const float* b5 = (const float*)d_in[10];
    const float* codebooks = (const float*)d_in[11];
    const float* head_w = (const float*)d_in[12];
    const float* head_b = (const float*)d_in[13];
    float* out = (float*)d_out;

    float *x1, *x2, *x3, *x4, *x5, *zqT, *w2T, *w3T, *w4T, *w5T, *hwT, *cnm, *part;
    cudaGetSymbolAddress((void**)&x1, g_x1);
    cudaGetSymbolAddress((void**)&x2, g_x2);
    cudaGetSymbolAddress((void**)&x3, g_x3);
    cudaGetSymbolAddress((void**)&x4, g_x4);
    cudaGetSymbolAddress((void**)&x5, g_x5);
    cudaGetSymbolAddress((void**)&zqT, g_zqT);
    cudaGetSymbolAddress((void**)&w2T, g_w2T);
    cudaGetSymbolAddress((void**)&w3T, g_w3T);
    cudaGetSymbolAddress((void**)&w4T, g_w4T);
    cudaGetSymbolAddress((void**)&w5T, g_w5T);
    cudaGetSymbolAddress((void**)&hwT, g_hwT);
    cudaGetSymbolAddress((void**)&cnm, g_cnorm);
    cudaGetSymbolAddress((void**)&part, g_part);

    // dynamic smem sizes (bytes): 3 stages of (CI_CHUNK*136 + CI_CHUNK*K*128)
    const int SM_C2 = (3 * (8 * 136 + 8 * 5 * 128)) * 4;            // 74496
    const int SM_C3 = SM_C2;                                        // 74496
    const int SM_C4 = (3 * (16 * 136 + 16 * 3 * 128)) * 4;          // 99840
    const int SM_C5 = SM_C4;                                        // 99840
    const int SM_HD = (3 * (16 * 136 + 16 * 1 * 128)) * 4;          // 50688

    cudaFuncSetAttribute((const void*)conv_gemm<64, 128, 5, 8, 1, 0>,
                         cudaFuncAttributeMaxDynamicSharedMemorySize, SM_C2);
    cudaFuncSetAttribute((const void*)conv_gemm<128, 256, 5, 8, 1, 0>,
                         cudaFuncAttributeMaxDynamicSharedMemorySize, SM_C3);
    cudaFuncSetAttribute((const void*)conv_gemm<256, 512, 3, 16, 1, 0>,
                         cudaFuncAttributeMaxDynamicSharedMemorySize, SM_C4);
    cudaFuncSetAttribute((const void*)conv_gemm<512, 512, 3, 16, 0, 0>,
                         cudaFuncAttributeMaxDynamicSharedMemorySize, SM_C5);
    cudaFuncSetAttribute((const void*)conv_gemm<512, 256, 1, 16, 0, 1>,
                         cudaFuncAttributeMaxDynamicSharedMemorySize, SM_HD);
    cudaFuncSetAttribute((const void*)vq_kernel,
                         cudaFuncAttributeMaxDynamicSharedMemorySize, VQ_BYTES);

    // fused weight prep + codebook norms (1 launch)
    prep_kernel<<<(N_PREP + 255) / 256, 256>>>(w2, w3, w4, w5, head_w, codebooks,
                                               w2T, w3T, w4T, w5T, hwT, cnm);

    // encoder
    conv1_kernel<<<dim3(32, 8), 128>>>(audio, w1, b1, x1);
    conv_gemm<64, 128, 5, 8, 1, 0><<<dim3(32, 1, 8), 256, SM_C2>>>(x1, w2T, b2, x2);
    conv_gemm<128, 256, 5, 8, 1, 0><<<dim3(32, 2, 8), 256, SM_C3>>>(x2, w3T, b3, x3);
    conv_gemm<256, 512, 3, 16, 1, 0><<<dim3(32, 4, 8), 256, SM_C4>>>(x3, w4T, b4, x4);
    conv_gemm<512, 512, 3, 16, 0, 0><<<dim3(32, 4, 8), 256, SM_C5>>>(x4, w5T, b5, x5);

    // VQ + heads + loss
    vq_kernel<<<dim3(32, 8, 8), 256, VQ_BYTES>>>(x5, codebooks, cnm,
                                                 zqT, out + OFF_A, part);
    conv_gemm<512, 256, 1, 16, 0, 1><<<dim3(32, 2, 8), 256, SM_HD>>>(zqT, hwT, head_b,
                                                                     out + OFF_B);
    loss_kernel<<<1, 256>>>(part, out);
}